// round 6
// baseline (speedup 1.0000x reference)
#include <cuda_runtime.h>

#define NG 768
#define H  128
typedef unsigned long long ull;

// Prep outputs, [k][gene]-major. i-side operands pre-DUPLICATED ({v,v}) for f32x2.
__device__ float g_AiT_dup[H * 2 * NG];  // (X@W1a^T + b1), dup
__device__ float g_YT_dup [H * 2 * NG];  // (X@Wb), dup
__device__ float g_BjT[H * NG];          // (X@W1b^T)
__device__ float g_XT [H * NG];          // X^T

__device__ __forceinline__ ull add2(ull a, ull b) {
    ull r; asm("add.rn.f32x2 %0, %1, %2;" : "=l"(r) : "l"(a), "l"(b)); return r;
}
__device__ __forceinline__ void fma2(ull& acc, ull a, ull b) {
    asm("fma.rn.f32x2 %0, %1, %2, %0;" : "+l"(acc) : "l"(a), "l"(b));
}
__device__ __forceinline__ float lo32(ull v) { return __uint_as_float((unsigned)v); }
__device__ __forceinline__ float hi32(ull v) { return __uint_as_float((unsigned)(v >> 32)); }

// ---------------- prep v3: thread = (gene-lane, t-oct) -------------------
// grid (48, 3), 256 threads. Block handles 16 genes for one matrix m.
__global__ __launch_bounds__(256)
void prep_gemm(const float* __restrict__ X, const float* __restrict__ W1,
               const float* __restrict__ b1, const float* __restrict__ Wb) {
    extern __shared__ float psm[];
    float* Ws = psm;               // [128][132], Ws[t][k]
    float* Xs = psm + 128 * 132;   // [16][132],  Xs[g][k]

    int tid = threadIdx.x;
    int m = blockIdx.y;
    int g0 = blockIdx.x * 16;

    if (m < 2) {
        const float4* W14 = (const float4*)W1;   // W1 [128][256]
        #pragma unroll
        for (int it = 0; it < 16; ++it) {
            int idx = tid + 256 * it;
            int t = idx >> 5, kc = idx & 31;
            *(float4*)&Ws[t * 132 + kc * 4] = W14[t * 64 + m * 32 + kc];
        }
    } else {
        #pragma unroll 8
        for (int it = 0; it < 64; ++it) {        // Ws[t][k] = Wb[k][t]
            int idx = tid + 256 * it;
            int k = idx >> 7, t = idx & 127;
            Ws[t * 132 + k] = Wb[k * H + t];
        }
    }
    {
        const float4* X4 = (const float4*)X;
        #pragma unroll
        for (int it = 0; it < 2; ++it) {
            int idx = tid + 256 * it;
            int g = idx >> 5, kc = idx & 31;
            *(float4*)&Xs[g * 132 + kc * 4] = X4[(g0 + g) * 32 + kc];
        }
    }
    __syncthreads();

    int g  = tid & 15;    // gene lane (coalesced stores, broadcast-free x)
    int tg = tid >> 4;    // t-oct
    int t0 = tg * 8;

    float acc[8];
    #pragma unroll
    for (int i = 0; i < 8; ++i) acc[i] = 0.f;

    #pragma unroll 4
    for (int k4 = 0; k4 < 32; ++k4) {
        float4 x = *(const float4*)&Xs[g * 132 + k4 * 4];
        #pragma unroll
        for (int i = 0; i < 8; ++i) {
            float4 w = *(const float4*)&Ws[(t0 + i) * 132 + k4 * 4];  // warp-broadcast
            acc[i] = fmaf(x.x, w.x, fmaf(x.y, w.y, fmaf(x.z, w.z, fmaf(x.w, w.w, acc[i]))));
        }
    }

    int gene = g0 + g;
    #pragma unroll
    for (int i = 0; i < 8; ++i) {
        int t = t0 + i;
        float v = acc[i];
        if (m == 0) {
            v += __ldg(&b1[t]);
            *(float2*)&g_AiT_dup[t * 2 * NG + 2 * gene] = make_float2(v, v);
        } else if (m == 1) {
            g_BjT[t * NG + gene] = v;
        } else {
            *(float2*)&g_YT_dup[t * 2 * NG + 2 * gene] = make_float2(v, v);
        }
    }

    if (m == 1) {
        #pragma unroll
        for (int it = 0; it < 8; ++it) {
            int idx = tid + 256 * it;
            int k = idx >> 4, gg = idx & 15;
            g_XT[k * NG + g0 + gg] = Xs[gg * 132 + k];
        }
    }
}

// ---------------- pair kernel: abs-identity + f32x2 ----------------------
// 64x64 tile, grid 12x12, 256 threads. d01 = 0.5*(sA0[i]+sB0[j]+Sum|t|wd0)+db01.
__global__ __launch_bounds__(256, 1)
void pair_kernel(const float* __restrict__ W2, const float* __restrict__ b2,
                 const float* __restrict__ bb, float* __restrict__ out) {
    extern __shared__ float sm[];
    float* AsD  = sm;                  // [128][128] dup'd Ai'
    float* YsD  = AsD + 128 * 128;     // [128][128] dup'd Y
    float* Bs   = YsD + 128 * 128;     // [128][64]
    float* Xs   = Bs  + 128 * 64;      // [128][64]
    float* wdd  = Xs  + 128 * 64;      // [128][4] = (wd0,wd0,wd1,wd1)
    float* sRed = wdd + 128 * 4;       // [2 khalf][4][64]: sA0,sA1,sB0,sB1 partials

    int tid = threadIdx.x;
    int bi = blockIdx.y, bj = blockIdx.x;

    const float4* A4 = (const float4*)g_AiT_dup;  // row = 384 float4
    const float4* Y4 = (const float4*)g_YT_dup;
    const float4* B4 = (const float4*)g_BjT;      // row = 192 float4
    const float4* X4 = (const float4*)g_XT;
    float4* AsD4 = (float4*)AsD;
    float4* YsD4 = (float4*)YsD;
    float4* Bs4  = (float4*)Bs;
    float4* Xs4  = (float4*)Xs;

    #pragma unroll
    for (int it = 0; it < 16; ++it) {            // 4096 float4 each
        int idx = tid + 256 * it;
        int k = idx >> 5, c = idx & 31;
        AsD4[idx] = A4[k * 384 + bi * 32 + c];
        YsD4[idx] = Y4[k * 384 + bi * 32 + c];
    }
    #pragma unroll
    for (int it = 0; it < 8; ++it) {             // 2048 float4 each
        int idx = tid + 256 * it;
        int k = idx >> 4, c = idx & 15;
        Bs4[idx] = B4[k * 192 + bj * 16 + c];
        Xs4[idx] = X4[k * 192 + bj * 16 + c];
    }
    if (tid < H) {
        float w0 = W2[tid], w1 = W2[H + tid], w2v = W2[2 * H + tid];
        ((float4*)wdd)[tid] = make_float4(w0 - w1, w0 - w1, w0 - w2v, w0 - w2v);
    }
    __syncthreads();

    // Prologue: factorized linear sums. k split in halves across thread groups.
    {
        int grp = tid >> 7;          // which k half
        int r   = tid & 127;
        float s0 = 0.f, s1 = 0.f;
        if (r < 64) {                // i side from dup'd tile
            #pragma unroll 4
            for (int k = 0; k < 64; ++k) {
                int kk = grp * 64 + k;
                float  v = AsD[kk * 128 + 2 * r];
                float4 w = ((const float4*)wdd)[kk];
                s0 = fmaf(v, w.x, s0);
                s1 = fmaf(v, w.z, s1);
            }
            sRed[grp * 256 + r]      = s0;   // sA0 partial
            sRed[grp * 256 + 64 + r] = s1;   // sA1 partial
        } else {                     // j side
            int lj = r - 64;
            #pragma unroll 4
            for (int k = 0; k < 64; ++k) {
                int kk = grp * 64 + k;
                float  v = Bs[kk * 64 + lj];
                float4 w = ((const float4*)wdd)[kk];
                s0 = fmaf(v, w.x, s0);
                s1 = fmaf(v, w.z, s1);
            }
            sRed[grp * 256 + 128 + lj] = s0; // sB0 partial
            sRed[grp * 256 + 192 + lj] = s1; // sB1 partial
        }
    }
    __syncthreads();

    int tx = tid & 15, ty = tid >> 4;

    const ulonglong2* AsL = (const ulonglong2*)AsD;  // row = 32 ull2
    const ulonglong2* YsL = (const ulonglong2*)YsD;
    const ulonglong2* BsL = (const ulonglong2*)Bs;   // row = 16 ull2
    const ulonglong2* XsL = (const ulonglong2*)Xs;
    const ulonglong2* WdL = (const ulonglong2*)wdd;

    ull a01[8], a02[8], aaf[8];
    #pragma unroll
    for (int r = 0; r < 8; ++r) { a01[r] = 0ULL; a02[r] = 0ULL; aaf[r] = 0ULL; }

    const ull ABS2 = 0x7FFFFFFF7FFFFFFFULL;

    // MLP loop: accumulate Sum_k |a+b| * wd  (packed over 2 j's)
    #pragma unroll 4
    for (int k = 0; k < H; ++k) {
        ulonglong2 ad0 = AsL[k * 32 + ty * 2];
        ulonglong2 ad1 = AsL[k * 32 + ty * 2 + 1];
        ulonglong2 bq  = BsL[k * 16 + tx];
        ulonglong2 wq  = WdL[k];
        ull a2[4] = {ad0.x, ad0.y, ad1.x, ad1.y};
        ull bv[2] = {bq.x, bq.y};
        #pragma unroll
        for (int p = 0; p < 4; ++p) {
            #pragma unroll
            for (int qp = 0; qp < 2; ++qp) {
                int r = p * 2 + qp;
                ull t = add2(a2[p], bv[qp]) & ABS2;   // |a+b| : 1 FADD2 + LOP3s
                fma2(a01[r], t, wq.x);
                fma2(a02[r], t, wq.y);
            }
        }
    }

    // Affinity loop (pure packed GEMM microkernel)
    #pragma unroll 4
    for (int k = 0; k < H; ++k) {
        ulonglong2 yd0 = YsL[k * 32 + ty * 2];
        ulonglong2 yd1 = YsL[k * 32 + ty * 2 + 1];
        ulonglong2 xq  = XsL[k * 16 + tx];
        ull y2[4] = {yd0.x, yd0.y, yd1.x, yd1.y};
        ull xv[2] = {xq.x, xq.y};
        #pragma unroll
        for (int p = 0; p < 4; ++p) {
            #pragma unroll
            for (int qp = 0; qp < 2; ++qp)
                fma2(aaf[p * 2 + qp], y2[p], xv[qp]);
        }
    }

    float db01 = b2[0] - b2[1];
    float db02 = b2[0] - b2[2];
    float bbv  = bb[0];

    #pragma unroll
    for (int p = 0; p < 4; ++p) {
        int li = ty * 4 + p;
        int gi = bi * 64 + li;
        float sA0v = sRed[li]       + sRed[256 + li];
        float sA1v = sRed[64 + li]  + sRed[256 + 64 + li];
        float ov[4];
        #pragma unroll
        for (int qp = 0; qp < 2; ++qp) {
            int r = p * 2 + qp;
            #pragma unroll
            for (int hh = 0; hh < 2; ++hh) {
                int ljj = tx * 4 + qp * 2 + hh;
                float sB0v = sRed[128 + ljj] + sRed[256 + 128 + ljj];
                float sB1v = sRed[192 + ljj] + sRed[256 + 192 + ljj];
                float P01 = hh ? hi32(a01[r]) : lo32(a01[r]);
                float P02 = hh ? hi32(a02[r]) : lo32(a02[r]);
                float Paf = hh ? hi32(aaf[r]) : lo32(aaf[r]);
                float d01 = fmaf(0.5f, sA0v + sB0v + P01, db01);  // l0-l1
                float d02 = fmaf(0.5f, sA1v + sB1v + P02, db02);  // l0-l2
                float af  = Paf + bbv;
                // argmax first-occurrence: cls0 <=> d01>=0 && d02>=0;
                // cls2 <=> d02<0 && d02<d01
                float s = (d01 >= 0.f && d02 >= 0.f) ? 1.f
                        : ((d02 < 0.f && d02 < d01) ? -1.f : 0.f);
                int gj = bj * 64 + ljj;
                ov[qp * 2 + hh] = (gi == gj) ? 0.f : s * af;
            }
        }
        float4 o; o.x = ov[0]; o.y = ov[1]; o.z = ov[2]; o.w = ov[3];
        *(float4*)&out[gi * NG + bj * 64 + tx * 4] = o;
    }
}

extern "C" void kernel_launch(void* const* d_in, const int* in_sizes, int n_in,
                              void* d_out, int out_size) {
    const float* X  = (const float*)d_in[0];
    const float* W1 = (const float*)d_in[1];
    const float* b1 = (const float*)d_in[2];
    const float* W2 = (const float*)d_in[3];
    const float* b2 = (const float*)d_in[4];
    const float* Wb = (const float*)d_in[5];
    const float* bb = (const float*)d_in[6];
    float* out = (float*)d_out;

    size_t psmem = (size_t)(128 * 132 + 16 * 132) * sizeof(float);
    cudaFuncSetAttribute(prep_gemm, cudaFuncAttributeMaxDynamicSharedMemorySize,
                         (int)psmem);
    size_t smem = (size_t)(2 * 128 * 128 + 2 * 128 * 64 + 128 * 4 + 512) * sizeof(float);
    cudaFuncSetAttribute(pair_kernel, cudaFuncAttributeMaxDynamicSharedMemorySize,
                         (int)smem);

    prep_gemm<<<dim3(48, 3), 256, psmem>>>(X, W1, b1, Wb);
    pair_kernel<<<dim3(12, 12), 256, smem>>>(W2, b2, bb, out);
}

// round 8
// speedup vs baseline: 1.4074x; 1.4074x over previous
#include <cuda_runtime.h>

#define NG 768
#define H  128
typedef unsigned long long ull;

// Prep outputs, [k][gene]-major. i-side operands pre-DUPLICATED ({v,v}) for f32x2.
__device__ float g_AiT_dup[H * 2 * NG];  // (X@W1a^T + b1), dup
__device__ float g_YT_dup [H * 2 * NG];  // (X@Wb), dup
__device__ float g_BjT[H * NG];          // (X@W1b^T)
__device__ float g_XT [H * NG];          // X^T

__device__ __forceinline__ ull add2(ull a, ull b) {
    ull r; asm("add.rn.f32x2 %0, %1, %2;" : "=l"(r) : "l"(a), "l"(b)); return r;
}
__device__ __forceinline__ void fma2(ull& acc, ull a, ull b) {
    asm("fma.rn.f32x2 %0, %1, %2, %0;" : "+l"(acc) : "l"(a), "l"(b));
}
__device__ __forceinline__ float lo32(ull v) { return __uint_as_float((unsigned)v); }
__device__ __forceinline__ float hi32(ull v) { return __uint_as_float((unsigned)(v >> 32)); }

// ---------------- prep (unchanged from R6, validated) --------------------
__global__ __launch_bounds__(256)
void prep_gemm(const float* __restrict__ X, const float* __restrict__ W1,
               const float* __restrict__ b1, const float* __restrict__ Wb) {
    extern __shared__ float psm[];
    float* Ws = psm;               // [128][132], Ws[t][k]
    float* Xs = psm + 128 * 132;   // [16][132],  Xs[g][k]

    int tid = threadIdx.x;
    int m = blockIdx.y;
    int g0 = blockIdx.x * 16;

    if (m < 2) {
        const float4* W14 = (const float4*)W1;   // W1 [128][256]
        #pragma unroll
        for (int it = 0; it < 16; ++it) {
            int idx = tid + 256 * it;
            int t = idx >> 5, kc = idx & 31;
            *(float4*)&Ws[t * 132 + kc * 4] = W14[t * 64 + m * 32 + kc];
        }
    } else {
        #pragma unroll 8
        for (int it = 0; it < 64; ++it) {        // Ws[t][k] = Wb[k][t]
            int idx = tid + 256 * it;
            int k = idx >> 7, t = idx & 127;
            Ws[t * 132 + k] = Wb[k * H + t];
        }
    }
    {
        const float4* X4 = (const float4*)X;
        #pragma unroll
        for (int it = 0; it < 2; ++it) {
            int idx = tid + 256 * it;
            int g = idx >> 5, kc = idx & 31;
            *(float4*)&Xs[g * 132 + kc * 4] = X4[(g0 + g) * 32 + kc];
        }
    }
    __syncthreads();

    int g  = tid & 15;
    int tg = tid >> 4;
    int t0 = tg * 8;

    float acc[8];
    #pragma unroll
    for (int i = 0; i < 8; ++i) acc[i] = 0.f;

    #pragma unroll 4
    for (int k4 = 0; k4 < 32; ++k4) {
        float4 x = *(const float4*)&Xs[g * 132 + k4 * 4];
        #pragma unroll
        for (int i = 0; i < 8; ++i) {
            float4 w = *(const float4*)&Ws[(t0 + i) * 132 + k4 * 4];
            acc[i] = fmaf(x.x, w.x, fmaf(x.y, w.y, fmaf(x.z, w.z, fmaf(x.w, w.w, acc[i]))));
        }
    }

    int gene = g0 + g;
    #pragma unroll
    for (int i = 0; i < 8; ++i) {
        int t = t0 + i;
        float v = acc[i];
        if (m == 0) {
            v += __ldg(&b1[t]);
            *(float2*)&g_AiT_dup[t * 2 * NG + 2 * gene] = make_float2(v, v);
        } else if (m == 1) {
            g_BjT[t * NG + gene] = v;
        } else {
            *(float2*)&g_YT_dup[t * 2 * NG + 2 * gene] = make_float2(v, v);
        }
    }

    if (m == 1) {
        #pragma unroll
        for (int it = 0; it < 8; ++it) {
            int idx = tid + 256 * it;
            int k = idx >> 4, gg = idx & 15;
            g_XT[k * NG + g0 + gg] = Xs[gg * 132 + k];
        }
    }
}

// ------------- pair kernel: 512 threads, fused loop, 2x4 microtile -------
__global__ __launch_bounds__(512, 1)
void pair_kernel(const float* __restrict__ W2, const float* __restrict__ b2,
                 const float* __restrict__ bb, float* __restrict__ out) {
    extern __shared__ float sm[];
    float* AsD   = sm;                  // [128][128] dup'd Ai'
    float* YsD   = AsD + 128 * 128;     // [128][128] dup'd Y
    float* Bs    = YsD + 128 * 128;     // [128][64]
    float* Xs    = Bs  + 128 * 64;      // [128][64]
    float* wdd   = Xs  + 128 * 64;      // [128][4] = (wd0,wd0,wd1,wd1)
    float* sPart = wdd + 128 * 4;       // [2 side][4 kq][2][64] partial sums

    int tid = threadIdx.x;
    int bi = blockIdx.y, bj = blockIdx.x;

    const float4* A4 = (const float4*)g_AiT_dup;  // row = 384 float4
    const float4* Y4 = (const float4*)g_YT_dup;
    const float4* B4 = (const float4*)g_BjT;      // row = 192 float4
    const float4* X4 = (const float4*)g_XT;
    float4* AsD4 = (float4*)AsD;
    float4* YsD4 = (float4*)YsD;
    float4* Bs4  = (float4*)Bs;
    float4* Xs4  = (float4*)Xs;

    #pragma unroll
    for (int it = 0; it < 8; ++it) {             // 4096 float4 each
        int idx = tid + 512 * it;
        int k = idx >> 5, c = idx & 31;
        AsD4[idx] = A4[k * 384 + bi * 32 + c];
        YsD4[idx] = Y4[k * 384 + bi * 32 + c];
    }
    #pragma unroll
    for (int it = 0; it < 4; ++it) {             // 2048 float4 each
        int idx = tid + 512 * it;
        int k = idx >> 4, c = idx & 15;
        Bs4[idx] = B4[k * 192 + bj * 16 + c];
        Xs4[idx] = X4[k * 192 + bj * 16 + c];
    }
    if (tid < H) {
        float w0 = W2[tid], w1 = W2[H + tid], w2v = W2[2 * H + tid];
        ((float4*)wdd)[tid] = make_float4(w0 - w1, w0 - w1, w0 - w2v, w0 - w2v);
    }
    __syncthreads();

    // Prologue: factorized linear sums (k-quarters across threads, uniform per warp).
    {
        int e    = tid & 63;          // entity (i or j) within tile
        int kq   = (tid >> 6) & 3;    // k quarter
        int side = tid >> 8;          // 0 = i-side, 1 = j-side
        float s0 = 0.f, s1 = 0.f;
        if (side == 0) {
            #pragma unroll 4
            for (int k = 0; k < 32; ++k) {
                int kk = kq * 32 + k;
                float  v = AsD[kk * 128 + 2 * e];
                float4 w = ((const float4*)wdd)[kk];
                s0 = fmaf(v, w.x, s0);
                s1 = fmaf(v, w.z, s1);
            }
        } else {
            #pragma unroll 4
            for (int k = 0; k < 32; ++k) {
                int kk = kq * 32 + k;
                float  v = Bs[kk * 64 + e];
                float4 w = ((const float4*)wdd)[kk];
                s0 = fmaf(v, w.x, s0);
                s1 = fmaf(v, w.z, s1);
            }
        }
        sPart[side * 512 + kq * 128 + e]      = s0;
        sPart[side * 512 + kq * 128 + 64 + e] = s1;
    }
    __syncthreads();

    int tx = tid & 15;     // 4 j's: j = tx*4..tx*4+3
    int ty = tid >> 4;     // 0..31: 2 i's: i = ty*2, ty*2+1

    const ulonglong2* AsL = (const ulonglong2*)AsD;  // row = 32 ull2
    const ulonglong2* YsL = (const ulonglong2*)YsD;
    const ulonglong2* BsL = (const ulonglong2*)Bs;   // row = 16 ull2
    const ulonglong2* XsL = (const ulonglong2*)Xs;
    const ulonglong2* WdL = (const ulonglong2*)wdd;

    ull a01[4], a02[4], aaf[4];
    #pragma unroll
    for (int r = 0; r < 4; ++r) { a01[r] = 0ULL; a02[r] = 0ULL; aaf[r] = 0ULL; }

    const ull ABS2 = 0x7FFFFFFF7FFFFFFFULL;

    // Fused loop: P01/P02 = Sum_k |a+b|*wd ; aaf = Sum_k y*x (all packed pairs)
    #pragma unroll 4
    for (int k = 0; k < H; ++k) {
        ulonglong2 ad = AsL[k * 32 + ty];   // dup'd: {i0,i0},{i1,i1}
        ulonglong2 yd = YsL[k * 32 + ty];
        ulonglong2 bq = BsL[k * 16 + tx];   // {j0,j1},{j2,j3}
        ulonglong2 xq = XsL[k * 16 + tx];
        ulonglong2 wq = WdL[k];
        ull a2[2] = {ad.x, ad.y};
        ull y2[2] = {yd.x, yd.y};
        ull bv[2] = {bq.x, bq.y};
        ull xv[2] = {xq.x, xq.y};
        #pragma unroll
        for (int p = 0; p < 2; ++p) {
            #pragma unroll
            for (int qp = 0; qp < 2; ++qp) {
                int r = p * 2 + qp;
                ull t = add2(a2[p], bv[qp]) & ABS2;   // |a+b|
                fma2(a01[r], t, wq.x);
                fma2(a02[r], t, wq.y);
                fma2(aaf[r], y2[p], xv[qp]);
            }
        }
    }

    float db01 = b2[0] - b2[1];
    float db02 = b2[0] - b2[2];
    float bbv  = bb[0];

    // Per-thread entity sums (reduce 4 k-quarter partials)
    float sB0v[4], sB1v[4];
    #pragma unroll
    for (int q = 0; q < 4; ++q) {
        int lj = tx * 4 + q;
        sB0v[q] = (sPart[512 + lj]       + sPart[512 + 128 + lj])
                + (sPart[512 + 256 + lj] + sPart[512 + 384 + lj]);
        sB1v[q] = (sPart[512 + 64 + lj]       + sPart[512 + 192 + lj])
                + (sPart[512 + 320 + lj] + sPart[512 + 448 + lj]);
    }

    #pragma unroll
    for (int p = 0; p < 2; ++p) {
        int li = ty * 2 + p;
        int gi = bi * 64 + li;
        float sA0v = (sPart[li]       + sPart[128 + li])
                   + (sPart[256 + li] + sPart[384 + li]);
        float sA1v = (sPart[64 + li]        + sPart[192 + li])
                   + (sPart[320 + li] + sPart[448 + li]);
        float ov[4];
        #pragma unroll
        for (int qp = 0; qp < 2; ++qp) {
            int r = p * 2 + qp;
            #pragma unroll
            for (int hh = 0; hh < 2; ++hh) {
                int q = qp * 2 + hh;
                float P01 = hh ? hi32(a01[r]) : lo32(a01[r]);
                float P02 = hh ? hi32(a02[r]) : lo32(a02[r]);
                float Paf = hh ? hi32(aaf[r]) : lo32(aaf[r]);
                float d01 = fmaf(0.5f, sA0v + sB0v[q] + P01, db01);  // l0-l1
                float d02 = fmaf(0.5f, sA1v + sB1v[q] + P02, db02);  // l0-l2
                float af  = Paf + bbv;
                // argmax first-occurrence: cls0 <=> d01>=0 && d02>=0;
                // cls2 <=> d02<0 && d02<d01
                float s = (d01 >= 0.f && d02 >= 0.f) ? 1.f
                        : ((d02 < 0.f && d02 < d01) ? -1.f : 0.f);
                int gj = bj * 64 + tx * 4 + q;
                ov[q] = (gi == gj) ? 0.f : s * af;
            }
        }
        float4 o; o.x = ov[0]; o.y = ov[1]; o.z = ov[2]; o.w = ov[3];
        *(float4*)&out[gi * NG + bj * 64 + tx * 4] = o;
    }
}

extern "C" void kernel_launch(void* const* d_in, const int* in_sizes, int n_in,
                              void* d_out, int out_size) {
    const float* X  = (const float*)d_in[0];
    const float* W1 = (const float*)d_in[1];
    const float* b1 = (const float*)d_in[2];
    const float* W2 = (const float*)d_in[3];
    const float* b2 = (const float*)d_in[4];
    const float* Wb = (const float*)d_in[5];
    const float* bb = (const float*)d_in[6];
    float* out = (float*)d_out;

    size_t psmem = (size_t)(128 * 132 + 16 * 132) * sizeof(float);
    cudaFuncSetAttribute(prep_gemm, cudaFuncAttributeMaxDynamicSharedMemorySize,
                         (int)psmem);
    size_t smem = (size_t)(2 * 128 * 128 + 2 * 128 * 64 + 128 * 4 + 1024) * sizeof(float);
    cudaFuncSetAttribute(pair_kernel, cudaFuncAttributeMaxDynamicSharedMemorySize,
                         (int)smem);

    prep_gemm<<<dim3(48, 3), 256, psmem>>>(X, W1, b1, Wb);
    pair_kernel<<<dim3(12, 12), 512, smem>>>(W2, b2, bb, out);
}

// round 9
// speedup vs baseline: 1.6407x; 1.1657x over previous
#include <cuda_runtime.h>

#define NG 768
#define H  128

// Prep outputs, [k][gene]-major (plain, no duplication).
__device__ float g_AiT[H * NG];  // (X@W1a^T + b1)^T
__device__ float g_YT [H * NG];  // (X@Wb)^T
__device__ float g_BjT[H * NG];  // (X@W1b^T)^T
__device__ float g_XT [H * NG];  // X^T

// ---------------- prep (R6 structure, non-dup stores) --------------------
__global__ __launch_bounds__(256)
void prep_gemm(const float* __restrict__ X, const float* __restrict__ W1,
               const float* __restrict__ b1, const float* __restrict__ Wb) {
    extern __shared__ float psm[];
    float* Ws = psm;               // [128][132], Ws[t][k]
    float* Xs = psm + 128 * 132;   // [16][132],  Xs[g][k]

    int tid = threadIdx.x;
    int m = blockIdx.y;
    int g0 = blockIdx.x * 16;

    if (m < 2) {
        const float4* W14 = (const float4*)W1;   // W1 [128][256]
        #pragma unroll
        for (int it = 0; it < 16; ++it) {
            int idx = tid + 256 * it;
            int t = idx >> 5, kc = idx & 31;
            *(float4*)&Ws[t * 132 + kc * 4] = W14[t * 64 + m * 32 + kc];
        }
    } else {
        #pragma unroll 8
        for (int it = 0; it < 64; ++it) {        // Ws[t][k] = Wb[k][t]
            int idx = tid + 256 * it;
            int k = idx >> 7, t = idx & 127;
            Ws[t * 132 + k] = Wb[k * H + t];
        }
    }
    {
        const float4* X4 = (const float4*)X;
        #pragma unroll
        for (int it = 0; it < 2; ++it) {
            int idx = tid + 256 * it;
            int g = idx >> 5, kc = idx & 31;
            *(float4*)&Xs[g * 132 + kc * 4] = X4[(g0 + g) * 32 + kc];
        }
    }
    __syncthreads();

    int g  = tid & 15;
    int tg = tid >> 4;
    int t0 = tg * 8;

    float acc[8];
    #pragma unroll
    for (int i = 0; i < 8; ++i) acc[i] = 0.f;

    #pragma unroll 4
    for (int k4 = 0; k4 < 32; ++k4) {
        float4 x = *(const float4*)&Xs[g * 132 + k4 * 4];
        #pragma unroll
        for (int i = 0; i < 8; ++i) {
            float4 w = *(const float4*)&Ws[(t0 + i) * 132 + k4 * 4];
            acc[i] = fmaf(x.x, w.x, fmaf(x.y, w.y, fmaf(x.z, w.z, fmaf(x.w, w.w, acc[i]))));
        }
    }

    int gene = g0 + g;
    #pragma unroll
    for (int i = 0; i < 8; ++i) {
        int t = t0 + i;
        float v = acc[i];
        if (m == 0) {
            g_AiT[t * NG + gene] = v + __ldg(&b1[t]);
        } else if (m == 1) {
            g_BjT[t * NG + gene] = v;
        } else {
            g_YT[t * NG + gene] = v;
        }
    }

    if (m == 1) {
        #pragma unroll
        for (int it = 0; it < 8; ++it) {
            int idx = tid + 256 * it;
            int k = idx >> 4, gg = idx & 15;
            g_XT[k * NG + g0 + gg] = Xs[gg * 132 + k];
        }
    }
}

// ------ pair kernel: scalar core, abs-identity, 512 thr, 2x4 microtile ---
// d01 = 0.5*(sA0[i]+sB0[j]+Sum_k |a+b|*wd0) + db01 ; likewise d02.
__global__ __launch_bounds__(512, 1)
void pair_kernel(const float* __restrict__ W2, const float* __restrict__ b2,
                 const float* __restrict__ bb, float* __restrict__ out) {
    extern __shared__ float sm[];
    float* As    = sm;                  // [128][64]
    float* Ys    = As + 128 * 64;       // [128][64]
    float* Bs    = Ys + 128 * 64;       // [128][64]
    float* Xs    = Bs + 128 * 64;       // [128][64]
    float* wd    = Xs + 128 * 64;       // [128][2] = (wd0, wd1)
    float* sPart = wd + 128 * 2;        // [2 side][4 kq][2][64] partial sums

    int tid = threadIdx.x;
    int bi = blockIdx.y, bj = blockIdx.x;

    const float4* A4g = (const float4*)g_AiT;  // row = 192 float4
    const float4* Y4g = (const float4*)g_YT;
    const float4* B4g = (const float4*)g_BjT;
    const float4* X4g = (const float4*)g_XT;
    float4* As4 = (float4*)As;
    float4* Ys4 = (float4*)Ys;
    float4* Bs4 = (float4*)Bs;
    float4* Xs4 = (float4*)Xs;

    #pragma unroll
    for (int it = 0; it < 4; ++it) {            // 2048 float4 each array
        int idx = tid + 512 * it;
        int k = idx >> 4, c = idx & 15;
        As4[idx] = A4g[k * 192 + bi * 16 + c];
        Ys4[idx] = Y4g[k * 192 + bi * 16 + c];
        Bs4[idx] = B4g[k * 192 + bj * 16 + c];
        Xs4[idx] = X4g[k * 192 + bj * 16 + c];
    }
    if (tid < H) {
        float w0 = W2[tid], w1 = W2[H + tid], w2v = W2[2 * H + tid];
        ((float2*)wd)[tid] = make_float2(w0 - w1, w0 - w2v);
    }
    __syncthreads();

    // Prologue: factorized linear sums, k-quarters across thread groups.
    {
        int e    = tid & 63;          // entity (i or j) within tile
        int kq   = (tid >> 6) & 3;    // k quarter
        int side = tid >> 8;          // 0 = i-side (As), 1 = j-side (Bs)
        const float* src = side ? Bs : As;
        float s0 = 0.f, s1 = 0.f;
        #pragma unroll 4
        for (int k = 0; k < 32; ++k) {
            int kk = kq * 32 + k;
            float  v = src[kk * 64 + e];
            float2 w = ((const float2*)wd)[kk];
            s0 = fmaf(v, w.x, s0);
            s1 = fmaf(v, w.y, s1);
        }
        sPart[side * 512 + kq * 128 + e]      = s0;
        sPart[side * 512 + kq * 128 + 64 + e] = s1;
    }
    __syncthreads();

    int tx = tid & 15;     // 4 j's: j = tx*4..tx*4+3
    int ty = tid >> 4;     // 0..31: 2 i's: i = ty*2, ty*2+1

    const float2* AsF2 = (const float2*)As;   // row = 32 float2
    const float2* YsF2 = (const float2*)Ys;
    const float2* WdF2 = (const float2*)wd;

    float a01[8], a02[8], aaf[8];
    #pragma unroll
    for (int r = 0; r < 8; ++r) { a01[r] = 0.f; a02[r] = 0.f; aaf[r] = 0.f; }

    // Fused scalar loop: P01/P02 = Sum_k |a+b|*wd ; aaf = Sum_k y*x
    #pragma unroll 4
    for (int k = 0; k < H; ++k) {
        float2 a = AsF2[k * 32 + ty];
        float2 y = YsF2[k * 32 + ty];
        float4 b = Bs4[k * 16 + tx];
        float4 x = Xs4[k * 16 + tx];
        float2 w = WdF2[k];
        float av[2] = {a.x, a.y};
        float yv[2] = {y.x, y.y};
        float bv[4] = {b.x, b.y, b.z, b.w};
        float xv[4] = {x.x, x.y, x.z, x.w};
        #pragma unroll
        for (int p = 0; p < 2; ++p) {
            #pragma unroll
            for (int q = 0; q < 4; ++q) {
                int r = p * 4 + q;
                float t = fabsf(av[p] + bv[q]);          // abs folds into FFMA srcmod
                a01[r] = fmaf(t, w.x, a01[r]);
                a02[r] = fmaf(t, w.y, a02[r]);
                aaf[r] = fmaf(yv[p], xv[q], aaf[r]);
            }
        }
    }

    float db01 = b2[0] - b2[1];
    float db02 = b2[0] - b2[2];
    float bbv  = bb[0];

    float sB0v[4], sB1v[4];
    #pragma unroll
    for (int q = 0; q < 4; ++q) {
        int lj = tx * 4 + q;
        sB0v[q] = (sPart[512 + lj]        + sPart[512 + 128 + lj])
                + (sPart[512 + 256 + lj]  + sPart[512 + 384 + lj]);
        sB1v[q] = (sPart[512 + 64 + lj]   + sPart[512 + 192 + lj])
                + (sPart[512 + 320 + lj]  + sPart[512 + 448 + lj]);
    }

    #pragma unroll
    for (int p = 0; p < 2; ++p) {
        int li = ty * 2 + p;
        int gi = bi * 64 + li;
        float sA0v = (sPart[li]        + sPart[128 + li])
                   + (sPart[256 + li]  + sPart[384 + li]);
        float sA1v = (sPart[64 + li]   + sPart[192 + li])
                   + (sPart[320 + li]  + sPart[448 + li]);
        float ov[4];
        #pragma unroll
        for (int q = 0; q < 4; ++q) {
            int r = p * 4 + q;
            float d01 = fmaf(0.5f, sA0v + sB0v[q] + a01[r], db01);  // l0-l1
            float d02 = fmaf(0.5f, sA1v + sB1v[q] + a02[r], db02);  // l0-l2
            float af  = aaf[r] + bbv;
            // argmax first-occurrence: cls0 <=> d01>=0 && d02>=0;
            // cls2 <=> d02<0 && d02<d01
            float s = (d01 >= 0.f && d02 >= 0.f) ? 1.f
                    : ((d02 < 0.f && d02 < d01) ? -1.f : 0.f);
            int gj = bj * 64 + tx * 4 + q;
            ov[q] = (gi == gj) ? 0.f : s * af;
        }
        float4 o; o.x = ov[0]; o.y = ov[1]; o.z = ov[2]; o.w = ov[3];
        *(float4*)&out[gi * NG + bj * 64 + tx * 4] = o;
    }
}

extern "C" void kernel_launch(void* const* d_in, const int* in_sizes, int n_in,
                              void* d_out, int out_size) {
    const float* X  = (const float*)d_in[0];
    const float* W1 = (const float*)d_in[1];
    const float* b1 = (const float*)d_in[2];
    const float* W2 = (const float*)d_in[3];
    const float* b2 = (const float*)d_in[4];
    const float* Wb = (const float*)d_in[5];
    const float* bb = (const float*)d_in[6];
    float* out = (float*)d_out;

    size_t psmem = (size_t)(128 * 132 + 16 * 132) * sizeof(float);
    cudaFuncSetAttribute(prep_gemm, cudaFuncAttributeMaxDynamicSharedMemorySize,
                         (int)psmem);
    size_t smem = (size_t)(4 * 128 * 64 + 128 * 2 + 1024) * sizeof(float);
    cudaFuncSetAttribute(pair_kernel, cudaFuncAttributeMaxDynamicSharedMemorySize,
                         (int)smem);

    prep_gemm<<<dim3(48, 3), 256, psmem>>>(X, W1, b1, Wb);
    pair_kernel<<<dim3(12, 12), 512, smem>>>(W2, b2, bb, out);
}

// round 10
// speedup vs baseline: 1.6425x; 1.0011x over previous
#include <cuda_runtime.h>
#include <cstdint>

#define NG 768
#define H  128

// Prep outputs, [k][gene]-major.
__device__ float g_AiT[H * NG];  // (X@W1a^T + b1)^T
__device__ float g_YT [H * NG];  // (X@Wb)^T
__device__ float g_BjT[H * NG];  // (X@W1b^T)^T
__device__ float g_XT [H * NG];  // X^T

__device__ __forceinline__ uint32_t tf32hi(float v) {
    uint32_t r; asm("cvt.rna.tf32.f32 %0, %1;" : "=r"(r) : "f"(v)); return r;
}
__device__ __forceinline__ void tf32split(float v, uint32_t& h, uint32_t& l) {
    h = tf32hi(v);
    l = tf32hi(v - __uint_as_float(h));
}
__device__ __forceinline__ void mma_tf32(float* d, const uint32_t* a, const uint32_t* b) {
    asm volatile("mma.sync.aligned.m16n8k8.row.col.f32.tf32.tf32.f32 "
        "{%0,%1,%2,%3}, {%4,%5,%6,%7}, {%8,%9}, {%0,%1,%2,%3};"
        : "+f"(d[0]), "+f"(d[1]), "+f"(d[2]), "+f"(d[3])
        : "r"(a[0]), "r"(a[1]), "r"(a[2]), "r"(a[3]), "r"(b[0]), "r"(b[1]));
}

// ---------------- prep (unchanged, validated) ----------------------------
__global__ __launch_bounds__(256)
void prep_gemm(const float* __restrict__ X, const float* __restrict__ W1,
               const float* __restrict__ b1, const float* __restrict__ Wb) {
    extern __shared__ float psm[];
    float* Ws = psm;               // [128][132], Ws[t][k]
    float* Xs = psm + 128 * 132;   // [16][132],  Xs[g][k]

    int tid = threadIdx.x;
    int m = blockIdx.y;
    int g0 = blockIdx.x * 16;

    if (m < 2) {
        const float4* W14 = (const float4*)W1;   // W1 [128][256]
        #pragma unroll
        for (int it = 0; it < 16; ++it) {
            int idx = tid + 256 * it;
            int t = idx >> 5, kc = idx & 31;
            *(float4*)&Ws[t * 132 + kc * 4] = W14[t * 64 + m * 32 + kc];
        }
    } else {
        #pragma unroll 8
        for (int it = 0; it < 64; ++it) {        // Ws[t][k] = Wb[k][t]
            int idx = tid + 256 * it;
            int k = idx >> 7, t = idx & 127;
            Ws[t * 132 + k] = Wb[k * H + t];
        }
    }
    {
        const float4* X4 = (const float4*)X;
        #pragma unroll
        for (int it = 0; it < 2; ++it) {
            int idx = tid + 256 * it;
            int g = idx >> 5, kc = idx & 31;
            *(float4*)&Xs[g * 132 + kc * 4] = X4[(g0 + g) * 32 + kc];
        }
    }
    __syncthreads();

    int g  = tid & 15;
    int tg = tid >> 4;
    int t0 = tg * 8;

    float acc[8];
    #pragma unroll
    for (int i = 0; i < 8; ++i) acc[i] = 0.f;

    #pragma unroll 4
    for (int k4 = 0; k4 < 32; ++k4) {
        float4 x = *(const float4*)&Xs[g * 132 + k4 * 4];
        #pragma unroll
        for (int i = 0; i < 8; ++i) {
            float4 w = *(const float4*)&Ws[(t0 + i) * 132 + k4 * 4];
            acc[i] = fmaf(x.x, w.x, fmaf(x.y, w.y, fmaf(x.z, w.z, fmaf(x.w, w.w, acc[i]))));
        }
    }

    int gene = g0 + g;
    #pragma unroll
    for (int i = 0; i < 8; ++i) {
        int t = t0 + i;
        float v = acc[i];
        if (m == 0) {
            g_AiT[t * NG + gene] = v + __ldg(&b1[t]);
        } else if (m == 1) {
            g_BjT[t * NG + gene] = v;
        } else {
            g_YT[t * NG + gene] = v;
        }
    }

    if (m == 1) {
        #pragma unroll
        for (int it = 0; it < 8; ++it) {
            int idx = tid + 256 * it;
            int k = idx >> 4, gg = idx & 15;
            g_XT[k * NG + g0 + gg] = Xs[gg * 132 + k];
        }
    }
}

// ---- pair kernel: scalar MLP loop + tensor-core (3xTF32) affinity -------
__global__ __launch_bounds__(512, 1)
void pair_kernel(const float* __restrict__ W2, const float* __restrict__ b2,
                 const float* __restrict__ bb, float* __restrict__ out) {
    extern __shared__ float sm[];
    float* As    = sm;                  // [128][64]
    float* Ys    = As + 128 * 64;       // [128][64]
    float* Bs    = Ys + 128 * 64;       // [128][64]
    float* Xs    = Bs + 128 * 64;       // [128][64]
    float* wd    = Xs + 128 * 64;       // [128][2] = (wd0, wd1)
    float* sPart = wd + 128 * 2;        // [2 side][4 kq][2][64] partial sums
    float* aff   = sPart + 1024;        // [64][68] bilinear affinity tile

    int tid = threadIdx.x;
    int bi = blockIdx.y, bj = blockIdx.x;

    const float4* A4g = (const float4*)g_AiT;  // row = 192 float4
    const float4* Y4g = (const float4*)g_YT;
    const float4* B4g = (const float4*)g_BjT;
    const float4* X4g = (const float4*)g_XT;
    float4* As4 = (float4*)As;
    float4* Ys4 = (float4*)Ys;
    float4* Bs4 = (float4*)Bs;
    float4* Xs4 = (float4*)Xs;

    #pragma unroll
    for (int it = 0; it < 4; ++it) {            // 2048 float4 each array
        int idx = tid + 512 * it;
        int k = idx >> 4, c = idx & 15;
        As4[idx] = A4g[k * 192 + bi * 16 + c];
        Ys4[idx] = Y4g[k * 192 + bi * 16 + c];
        Bs4[idx] = B4g[k * 192 + bj * 16 + c];
        Xs4[idx] = X4g[k * 192 + bj * 16 + c];
    }
    if (tid < H) {
        float w0 = W2[tid], w1 = W2[H + tid], w2v = W2[2 * H + tid];
        ((float2*)wd)[tid] = make_float2(w0 - w1, w0 - w2v);
    }
    __syncthreads();

    // Prologue A: factorized linear sums, k-quarters across thread groups.
    {
        int e    = tid & 63;
        int kq   = (tid >> 6) & 3;
        int side = tid >> 8;
        const float* src = side ? Bs : As;
        float s0 = 0.f, s1 = 0.f;
        #pragma unroll 4
        for (int k = 0; k < 32; ++k) {
            int kk = kq * 32 + k;
            float  v = src[kk * 64 + e];
            float2 w = ((const float2*)wd)[kk];
            s0 = fmaf(v, w.x, s0);
            s1 = fmaf(v, w.y, s1);
        }
        sPart[side * 512 + kq * 128 + e]      = s0;
        sPart[side * 512 + kq * 128 + 64 + e] = s1;
    }

    // Prologue B: affinity tile aff[i][j] = Sum_k Y[i,k]*X[j,k] via 3xTF32 mma.
    // Warp w: m-tile = (w&3)*16 rows, n-tiles (w>>2)*16 + {0,8}.
    {
        int w    = tid >> 5;
        int lane = tid & 31;
        int gid  = lane >> 2;      // 0..7
        int tig  = lane & 3;       // 0..3
        int mOff  = (w & 3) * 16;
        int nBase = (w >> 2) * 16;
        float d0[4] = {0.f, 0.f, 0.f, 0.f};
        float d1[4] = {0.f, 0.f, 0.f, 0.f};
        #pragma unroll 4
        for (int ks = 0; ks < 16; ++ks) {
            int k0 = ks * 8 + tig;
            uint32_t ah[4], al[4];
            tf32split(Ys[k0 * 64 + mOff + gid],           ah[0], al[0]);
            tf32split(Ys[k0 * 64 + mOff + gid + 8],       ah[1], al[1]);
            tf32split(Ys[(k0 + 4) * 64 + mOff + gid],     ah[2], al[2]);
            tf32split(Ys[(k0 + 4) * 64 + mOff + gid + 8], ah[3], al[3]);
            uint32_t bh[2], bl[2];
            tf32split(Xs[k0 * 64 + nBase + gid],       bh[0], bl[0]);
            tf32split(Xs[(k0 + 4) * 64 + nBase + gid], bh[1], bl[1]);
            mma_tf32(d0, ah, bh);
            mma_tf32(d0, ah, bl);
            mma_tf32(d0, al, bh);
            tf32split(Xs[k0 * 64 + nBase + 8 + gid],       bh[0], bl[0]);
            tf32split(Xs[(k0 + 4) * 64 + nBase + 8 + gid], bh[1], bl[1]);
            mma_tf32(d1, ah, bh);
            mma_tf32(d1, ah, bl);
            mma_tf32(d1, al, bh);
        }
        // Store D fragments (m16n8 layout: rows gid/gid+8, cols 2*tig, 2*tig+1)
        aff[(mOff + gid)     * 68 + nBase + 2 * tig]     = d0[0];
        aff[(mOff + gid)     * 68 + nBase + 2 * tig + 1] = d0[1];
        aff[(mOff + gid + 8) * 68 + nBase + 2 * tig]     = d0[2];
        aff[(mOff + gid + 8) * 68 + nBase + 2 * tig + 1] = d0[3];
        aff[(mOff + gid)     * 68 + nBase + 8 + 2 * tig]     = d1[0];
        aff[(mOff + gid)     * 68 + nBase + 8 + 2 * tig + 1] = d1[1];
        aff[(mOff + gid + 8) * 68 + nBase + 8 + 2 * tig]     = d1[2];
        aff[(mOff + gid + 8) * 68 + nBase + 8 + 2 * tig + 1] = d1[3];
    }
    __syncthreads();

    int tx = tid & 15;     // 4 j's: j = tx*4..tx*4+3
    int ty = tid >> 4;     // 0..31: 2 i's: i = ty*2, ty*2+1

    const float2* AsF2 = (const float2*)As;   // row = 32 float2
    const float2* WdF2 = (const float2*)wd;

    float a01[8], a02[8];
    #pragma unroll
    for (int r = 0; r < 8; ++r) { a01[r] = 0.f; a02[r] = 0.f; }

    // Main loop (MLP only): P01/P02 = Sum_k |a+b|*wd
    #pragma unroll 4
    for (int k = 0; k < H; ++k) {
        float2 a = AsF2[k * 32 + ty];
        float4 b = Bs4[k * 16 + tx];
        float2 w = WdF2[k];
        float av[2] = {a.x, a.y};
        float bv[4] = {b.x, b.y, b.z, b.w};
        #pragma unroll
        for (int p = 0; p < 2; ++p) {
            #pragma unroll
            for (int q = 0; q < 4; ++q) {
                int r = p * 4 + q;
                float t = fabsf(av[p] + bv[q]);   // abs folds into FFMA srcmod
                a01[r] = fmaf(t, w.x, a01[r]);
                a02[r] = fmaf(t, w.y, a02[r]);
            }
        }
    }

    float db01 = b2[0] - b2[1];
    float db02 = b2[0] - b2[2];
    float bbv  = bb[0];

    float sB0v[4], sB1v[4];
    #pragma unroll
    for (int q = 0; q < 4; ++q) {
        int lj = tx * 4 + q;
        sB0v[q] = (sPart[512 + lj]        + sPart[512 + 128 + lj])
                + (sPart[512 + 256 + lj]  + sPart[512 + 384 + lj]);
        sB1v[q] = (sPart[512 + 64 + lj]   + sPart[512 + 192 + lj])
                + (sPart[512 + 320 + lj]  + sPart[512 + 448 + lj]);
    }

    #pragma unroll
    for (int p = 0; p < 2; ++p) {
        int li = ty * 2 + p;
        int gi = bi * 64 + li;
        float sA0v = (sPart[li]        + sPart[128 + li])
                   + (sPart[256 + li]  + sPart[384 + li]);
        float sA1v = (sPart[64 + li]   + sPart[192 + li])
                   + (sPart[320 + li]  + sPart[448 + li]);
        float4 afq = *(const float4*)&aff[li * 68 + tx * 4];
        float afv[4] = {afq.x, afq.y, afq.z, afq.w};
        float ov[4];
        #pragma unroll
        for (int q = 0; q < 4; ++q) {
            int r = p * 4 + q;
            float d01 = fmaf(0.5f, sA0v + sB0v[q] + a01[r], db01);  // l0-l1
            float d02 = fmaf(0.5f, sA1v + sB1v[q] + a02[r], db02);  // l0-l2
            float af  = afv[q] + bbv;
            // argmax first-occurrence: cls0 <=> d01>=0 && d02>=0;
            // cls2 <=> d02<0 && d02<d01
            float s = (d01 >= 0.f && d02 >= 0.f) ? 1.f
                    : ((d02 < 0.f && d02 < d01) ? -1.f : 0.f);
            int gj = bj * 64 + tx * 4 + q;
            ov[q] = (gi == gj) ? 0.f : s * af;
        }
        float4 o; o.x = ov[0]; o.y = ov[1]; o.z = ov[2]; o.w = ov[3];
        *(float4*)&out[gi * NG + bj * 64 + tx * 4] = o;
    }
}

extern "C" void kernel_launch(void* const* d_in, const int* in_sizes, int n_in,
                              void* d_out, int out_size) {
    const float* X  = (const float*)d_in[0];
    const float* W1 = (const float*)d_in[1];
    const float* b1 = (const float*)d_in[2];
    const float* W2 = (const float*)d_in[3];
    const float* b2 = (const float*)d_in[4];
    const float* Wb = (const float*)d_in[5];
    const float* bb = (const float*)d_in[6];
    float* out = (float*)d_out;

    size_t psmem = (size_t)(128 * 132 + 16 * 132) * sizeof(float);
    cudaFuncSetAttribute(prep_gemm, cudaFuncAttributeMaxDynamicSharedMemorySize,
                         (int)psmem);
    size_t smem = (size_t)(4 * 128 * 64 + 128 * 2 + 1024 + 64 * 68) * sizeof(float);
    cudaFuncSetAttribute(pair_kernel, cudaFuncAttributeMaxDynamicSharedMemorySize,
                         (int)smem);

    prep_gemm<<<dim3(48, 3), 256, psmem>>>(X, W1, b1, Wb);
    pair_kernel<<<dim3(12, 12), 512, smem>>>(W2, b2, bb, out);
}

// round 12
// speedup vs baseline: 1.7092x; 1.0406x over previous
#include <cuda_runtime.h>
#include <cstdint>

#define NG 768
#define H  128

// Prep outputs, [k][gene]-major.
__device__ float g_AiT[H * NG];  // (X@W1a^T + b1)^T
__device__ float g_YT [H * NG];  // (X@Wb)^T
__device__ float g_BjT[H * NG];  // (X@W1b^T)^T
__device__ float g_XT [H * NG];  // X^T

__device__ __forceinline__ float tf32f(float v) {
    uint32_t r; asm("cvt.rna.tf32.f32 %0, %1;" : "=r"(r) : "f"(v));
    return __uint_as_float(r);
}
__device__ __forceinline__ void mma_tf32(float* d, const uint32_t* a, const uint32_t* b) {
    asm volatile("mma.sync.aligned.m16n8k8.row.col.f32.tf32.tf32.f32 "
        "{%0,%1,%2,%3}, {%4,%5,%6,%7}, {%8,%9}, {%0,%1,%2,%3};"
        : "+f"(d[0]), "+f"(d[1]), "+f"(d[2]), "+f"(d[3])
        : "r"(a[0]), "r"(a[1]), "r"(a[2]), "r"(a[3]), "r"(b[0]), "r"(b[1]));
}

// ---------------- prep (unchanged, validated) ----------------------------
__global__ __launch_bounds__(256)
void prep_gemm(const float* __restrict__ X, const float* __restrict__ W1,
               const float* __restrict__ b1, const float* __restrict__ Wb) {
    extern __shared__ float psm[];
    float* Ws = psm;               // [128][132], Ws[t][k]
    float* Xs = psm + 128 * 132;   // [16][132],  Xs[g][k]

    int tid = threadIdx.x;
    int m = blockIdx.y;
    int g0 = blockIdx.x * 16;

    if (m < 2) {
        const float4* W14 = (const float4*)W1;   // W1 [128][256]
        #pragma unroll
        for (int it = 0; it < 16; ++it) {
            int idx = tid + 256 * it;
            int t = idx >> 5, kc = idx & 31;
            *(float4*)&Ws[t * 132 + kc * 4] = W14[t * 64 + m * 32 + kc];
        }
    } else {
        #pragma unroll 8
        for (int it = 0; it < 64; ++it) {        // Ws[t][k] = Wb[k][t]
            int idx = tid + 256 * it;
            int k = idx >> 7, t = idx & 127;
            Ws[t * 132 + k] = Wb[k * H + t];
        }
    }
    {
        const float4* X4 = (const float4*)X;
        #pragma unroll
        for (int it = 0; it < 2; ++it) {
            int idx = tid + 256 * it;
            int g = idx >> 5, kc = idx & 31;
            *(float4*)&Xs[g * 132 + kc * 4] = X4[(g0 + g) * 32 + kc];
        }
    }
    __syncthreads();

    int g  = tid & 15;
    int tg = tid >> 4;
    int t0 = tg * 8;

    float acc[8];
    #pragma unroll
    for (int i = 0; i < 8; ++i) acc[i] = 0.f;

    #pragma unroll 4
    for (int k4 = 0; k4 < 32; ++k4) {
        float4 x = *(const float4*)&Xs[g * 132 + k4 * 4];
        #pragma unroll
        for (int i = 0; i < 8; ++i) {
            float4 w = *(const float4*)&Ws[(t0 + i) * 132 + k4 * 4];
            acc[i] = fmaf(x.x, w.x, fmaf(x.y, w.y, fmaf(x.z, w.z, fmaf(x.w, w.w, acc[i]))));
        }
    }

    int gene = g0 + g;
    #pragma unroll
    for (int i = 0; i < 8; ++i) {
        int t = t0 + i;
        float v = acc[i];
        if (m == 0) {
            g_AiT[t * NG + gene] = v + __ldg(&b1[t]);
        } else if (m == 1) {
            g_BjT[t * NG + gene] = v;
        } else {
            g_YT[t * NG + gene] = v;
        }
    }

    if (m == 1) {
        #pragma unroll
        for (int it = 0; it < 8; ++it) {
            int idx = tid + 256 * it;
            int k = idx >> 4, gg = idx & 15;
            g_XT[k * NG + g0 + gg] = Xs[gg * 132 + k];
        }
    }
}

// ---- pair kernel: warp-specialized (8 MLP warps + 8 mma warps) ----------
__global__ __launch_bounds__(512, 1)
void pair_kernel(const float* __restrict__ W2, const float* __restrict__ b2,
                 const float* __restrict__ bb, float* __restrict__ out) {
    extern __shared__ float sm[];
    float* As    = sm;                  // [128][64] k-major Ai'
    float* Bs    = As + 128 * 64;       // [128][64] k-major Bj
    float* wd    = Bs + 128 * 64;       // [128][2] = (wd0, wd1)
    float* sPart = wd + 128 * 2;        // [2 side][4 kq][2][64] partials
    float* aff   = sPart + 1024;        // [64][68] bilinear affinity
    float* Yhi   = aff + 64 * 68;       // [64][133] gene-major, pad-133
    float* Ylo   = Yhi + 64 * 133;
    float* Xhi   = Ylo + 64 * 133;
    float* Xlo   = Xhi + 64 * 133;

    int tid = threadIdx.x;
    int w    = tid >> 5;
    int lane = tid & 31;
    int bi = blockIdx.y, bj = blockIdx.x;
    int bi64 = bi * 64, bj64 = bj * 64;

    const float4* A4g = (const float4*)g_AiT;  // row = 192 float4
    const float4* B4g = (const float4*)g_BjT;
    float4* As4 = (float4*)As;
    float4* Bs4 = (float4*)Bs;

    #pragma unroll
    for (int it = 0; it < 4; ++it) {            // 2048 float4 each
        int idx = tid + 512 * it;
        int k = idx >> 4, c = idx & 15;
        As4[idx] = A4g[k * 192 + bi * 16 + c];
        Bs4[idx] = B4g[k * 192 + bj * 16 + c];
    }
    if (tid < H) {
        float w0 = W2[tid], w1 = W2[H + tid], w2v = W2[2 * H + tid];
        ((float2*)wd)[tid] = make_float2(w0 - w1, w0 - w2v);
    }
    // Convert phase: gmem -> tf32 hi/lo smem (gene-major, pad-133 => bank
    // (5g+k)&31, conflict-free writes since lanes span consecutive g).
    #pragma unroll
    for (int it = 0; it < 16; ++it) {
        int idx = tid + 512 * it;
        int g = idx & 63, k = idx >> 6;
        float yv = g_YT[k * NG + bi64 + g];
        float yh = tf32f(yv);
        Yhi[g * 133 + k] = yh;
        Ylo[g * 133 + k] = tf32f(yv - yh);
        float xv = g_XT[k * NG + bj64 + g];
        float xh = tf32f(xv);
        Xhi[g * 133 + k] = xh;
        Xlo[g * 133 + k] = tf32f(xv - xh);
    }
    __syncthreads();

    // Prologue A: factorized linear sums (all 16 warps, k-quarter split).
    {
        int e    = tid & 63;
        int kq   = (tid >> 6) & 3;
        int side = tid >> 8;
        const float* src = side ? Bs : As;
        float s0 = 0.f, s1 = 0.f;
        #pragma unroll 4
        for (int k = 0; k < 32; ++k) {
            int kk = kq * 32 + k;
            float  v = src[kk * 64 + e];
            float2 ww = ((const float2*)wd)[kk];
            s0 = fmaf(v, ww.x, s0);
            s1 = fmaf(v, ww.y, s1);
        }
        sPart[side * 512 + kq * 128 + e]      = s0;
        sPart[side * 512 + kq * 128 + 64 + e] = s1;
    }

    float a01[16], a02[16];
    int ig = lane >> 4;       // MLP: i-group
    int jg = lane & 15;       // MLP: j-group
    int i0 = w * 8 + ig * 4;
    int j0 = jg * 4;

    if (w < 8) {
        // ---- MLP warps: P01/P02 = Sum_k |a+b| * wd, 4i x 4j per thread ----
        #pragma unroll
        for (int r = 0; r < 16; ++r) { a01[r] = 0.f; a02[r] = 0.f; }
        const float2* WdF2 = (const float2*)wd;
        #pragma unroll 4
        for (int k = 0; k < H; ++k) {
            float4 a = As4[k * 16 + w * 2 + ig];
            float4 b = Bs4[k * 16 + jg];
            float2 ww = WdF2[k];
            float av[4] = {a.x, a.y, a.z, a.w};
            float bv[4] = {b.x, b.y, b.z, b.w};
            #pragma unroll
            for (int p = 0; p < 4; ++p) {
                #pragma unroll
                for (int q = 0; q < 4; ++q) {
                    int r = p * 4 + q;
                    float t = fabsf(av[p] + bv[q]);   // abs = FFMA srcmod
                    a01[r] = fmaf(t, ww.x, a01[r]);
                    a02[r] = fmaf(t, ww.y, a02[r]);
                }
            }
        }
    } else {
        // ---- mma warps: aff = Y @ X^T via 3xTF32, m16n32 per warp ----
        int wi   = w - 8;
        int gid  = lane >> 2;      // 0..7
        int tig  = lane & 3;       // 0..3
        int mOff = (wi & 3) * 16;
        int nOff = (wi >> 2) * 32;
        float d[16];
        #pragma unroll
        for (int r = 0; r < 16; ++r) d[r] = 0.f;
        #pragma unroll 2
        for (int ks = 0; ks < 16; ++ks) {
            int k0 = ks * 8 + tig;
            uint32_t ah[4], al[4];
            ah[0] = __float_as_uint(Yhi[(mOff + gid)     * 133 + k0]);
            ah[1] = __float_as_uint(Yhi[(mOff + gid + 8) * 133 + k0]);
            ah[2] = __float_as_uint(Yhi[(mOff + gid)     * 133 + k0 + 4]);
            ah[3] = __float_as_uint(Yhi[(mOff + gid + 8) * 133 + k0 + 4]);
            al[0] = __float_as_uint(Ylo[(mOff + gid)     * 133 + k0]);
            al[1] = __float_as_uint(Ylo[(mOff + gid + 8) * 133 + k0]);
            al[2] = __float_as_uint(Ylo[(mOff + gid)     * 133 + k0 + 4]);
            al[3] = __float_as_uint(Ylo[(mOff + gid + 8) * 133 + k0 + 4]);
            #pragma unroll
            for (int n8 = 0; n8 < 4; ++n8) {
                int nb = nOff + n8 * 8;
                uint32_t bh[2], bl[2];
                bh[0] = __float_as_uint(Xhi[(nb + gid) * 133 + k0]);
                bh[1] = __float_as_uint(Xhi[(nb + gid) * 133 + k0 + 4]);
                bl[0] = __float_as_uint(Xlo[(nb + gid) * 133 + k0]);
                bl[1] = __float_as_uint(Xlo[(nb + gid) * 133 + k0 + 4]);
                mma_tf32(&d[n8 * 4], ah, bh);
                mma_tf32(&d[n8 * 4], ah, bl);
                mma_tf32(&d[n8 * 4], al, bh);
            }
        }
        #pragma unroll
        for (int n8 = 0; n8 < 4; ++n8) {
            int nb = nOff + n8 * 8;
            aff[(mOff + gid)     * 68 + nb + 2 * tig]     = d[n8 * 4 + 0];
            aff[(mOff + gid)     * 68 + nb + 2 * tig + 1] = d[n8 * 4 + 1];
            aff[(mOff + gid + 8) * 68 + nb + 2 * tig]     = d[n8 * 4 + 2];
            aff[(mOff + gid + 8) * 68 + nb + 2 * tig + 1] = d[n8 * 4 + 3];
        }
    }
    __syncthreads();

    if (w < 8) {
        float db01 = b2[0] - b2[1];
        float db02 = b2[0] - b2[2];
        float bbv  = bb[0];

        float sB0v[4], sB1v[4];
        #pragma unroll
        for (int q = 0; q < 4; ++q) {
            int lj = j0 + q;
            sB0v[q] = (sPart[512 + lj]        + sPart[512 + 128 + lj])
                    + (sPart[512 + 256 + lj]  + sPart[512 + 384 + lj]);
            sB1v[q] = (sPart[512 + 64 + lj]   + sPart[512 + 192 + lj])
                    + (sPart[512 + 320 + lj]  + sPart[512 + 448 + lj]);
        }
        #pragma unroll
        for (int p = 0; p < 4; ++p) {
            int li = i0 + p;
            int gi = bi64 + li;
            float sA0v = (sPart[li]        + sPart[128 + li])
                       + (sPart[256 + li]  + sPart[384 + li]);
            float sA1v = (sPart[64 + li]   + sPart[192 + li])
                       + (sPart[320 + li]  + sPart[448 + li]);
            float4 afq = *(const float4*)&aff[li * 68 + j0];
            float afv[4] = {afq.x, afq.y, afq.z, afq.w};
            float ov[4];
            #pragma unroll
            for (int q = 0; q < 4; ++q) {
                int r = p * 4 + q;
                float d01 = fmaf(0.5f, sA0v + sB0v[q] + a01[r], db01);  // l0-l1
                float d02 = fmaf(0.5f, sA1v + sB1v[q] + a02[r], db02);  // l0-l2
                float af  = afv[q] + bbv;
                // argmax first-occurrence: cls0 <=> d01>=0 && d02>=0;
                // cls2 <=> d02<0 && d02<d01
                float s = (d01 >= 0.f && d02 >= 0.f) ? 1.f
                        : ((d02 < 0.f && d02 < d01) ? -1.f : 0.f);
                int gj = bj64 + j0 + q;
                ov[q] = (gi == gj) ? 0.f : s * af;
            }
            float4 o; o.x = ov[0]; o.y = ov[1]; o.z = ov[2]; o.w = ov[3];
            *(float4*)&out[gi * NG + bj64 + j0] = o;
        }
    }
}

extern "C" void kernel_launch(void* const* d_in, const int* in_sizes, int n_in,
                              void* d_out, int out_size) {
    const float* X  = (const float*)d_in[0];
    const float* W1 = (const float*)d_in[1];
    const float* b1 = (const float*)d_in[2];
    const float* W2 = (const float*)d_in[3];
    const float* b2 = (const float*)d_in[4];
    const float* Wb = (const float*)d_in[5];
    const float* bb = (const float*)d_in[6];
    float* out = (float*)d_out;

    size_t psmem = (size_t)(128 * 132 + 16 * 132) * sizeof(float);
    cudaFuncSetAttribute(prep_gemm, cudaFuncAttributeMaxDynamicSharedMemorySize,
                         (int)psmem);
    size_t smem = (size_t)(2 * 128 * 64 + 128 * 2 + 1024 + 64 * 68
                           + 4 * 64 * 133) * sizeof(float);
    cudaFuncSetAttribute(pair_kernel, cudaFuncAttributeMaxDynamicSharedMemorySize,
                         (int)smem);

    prep_gemm<<<dim3(48, 3), 256, psmem>>>(X, W1, b1, Wb);
    pair_kernel<<<dim3(12, 12), 512, smem>>>(W2, b2, bb, out);
}